// round 1
// baseline (speedup 1.0000x reference)
#include <cuda_runtime.h>

// ---------------- problem constants ----------------
#define WSZ   7
#define NW    8                    // windows per side (56/7)
#define HEADS 6
#define HD    32
#define NB    16
#define HW    56
#define DIM   192
#define NTOK  (NB*HW*HW)           // 50176
#define WTOK  (WSZ*WSZ)            // 49
#define QT    (NB*HEADS*NW*NW*WTOK*HD)   // 9,633,792 floats per tensor

// scratch (device globals; no allocation allowed)
__device__ float g_qkv[3u * QT];   // q | k | v in window layout [b,h,win,49,32]
__device__ float g_att[QT];        // attention output, same layout

// ================= Kernel 1: fused roll + QKV GEMM =================
// C[row, n] = sum_k x[b, (y+3)%56, (x+3)%56, k] * wqkv[k, n]
// scattered into window layout.
__global__ __launch_bounds__(256) void qkv_gemm(
    const float* __restrict__ x, const float* __restrict__ wqkv)
{
    __shared__ float As[16 * 68];   // A transposed: As[k][m]
    __shared__ float Bs[16 * 68];   // Bs[k][n]

    const int tid = threadIdx.x;
    const int bm  = blockIdx.x * 64;
    const int bn  = blockIdx.y * 64;
    const int tx  = tid & 15, ty = tid >> 4;

    // A-load mapping: thread -> (row m, k-quad)
    const int am  = tid >> 2;            // 0..63
    const int ak  = (tid & 3) * 4;       // 0,4,8,12
    {
        // decode row once (fixed across k-chunks)
    }
    int row = bm + am;
    int b   = row / 3136; int r = row - b * 3136;
    int y   = r / 56;     int xx = r - y * 56;
    int ys  = y + 3;  if (ys >= 56) ys -= 56;   // shifted-window roll on read
    int xs  = xx + 3; if (xs >= 56) xs -= 56;
    const float* aptr = x + ((b * 56 + ys) * 56 + xs) * 192 + ak;

    // B-load mapping
    const int bk  = tid >> 4;            // 0..15
    const int bn4 = (tid & 15) * 4;
    const float* bptr = wqkv + bk * 576 + bn + bn4;

    float acc[4][4] = {};

    for (int k0 = 0; k0 < 192; k0 += 16) {
        float4 av = *(const float4*)(aptr + k0);
        float4 bv = *(const float4*)(bptr + k0 * 576);
        __syncthreads();
        As[(ak + 0) * 68 + am] = av.x;
        As[(ak + 1) * 68 + am] = av.y;
        As[(ak + 2) * 68 + am] = av.z;
        As[(ak + 3) * 68 + am] = av.w;
        *(float4*)(Bs + bk * 68 + bn4) = bv;
        __syncthreads();
#pragma unroll
        for (int k = 0; k < 16; k++) {
            float4 a  = *(const float4*)(As + k * 68 + ty * 4);
            float4 bb = *(const float4*)(Bs + k * 68 + tx * 4);
            acc[0][0] += a.x * bb.x; acc[0][1] += a.x * bb.y;
            acc[0][2] += a.x * bb.z; acc[0][3] += a.x * bb.w;
            acc[1][0] += a.y * bb.x; acc[1][1] += a.y * bb.y;
            acc[1][2] += a.y * bb.z; acc[1][3] += a.y * bb.w;
            acc[2][0] += a.z * bb.x; acc[2][1] += a.z * bb.y;
            acc[2][2] += a.z * bb.z; acc[2][3] += a.z * bb.w;
            acc[3][0] += a.w * bb.x; acc[3][1] += a.w * bb.y;
            acc[3][2] += a.w * bb.z; acc[3][3] += a.w * bb.w;
        }
    }

    // epilogue: scatter into window layout. Columns: 4 consecutive, same head.
    const int n0g = bn + tx * 4;
    const int t   = n0g / 192;           // q/k/v selector (constant per block)
    const int c   = n0g - t * 192;
    const int h   = c >> 5, d = c & 31;
    float* qbase = g_qkv + t * QT;
#pragma unroll
    for (int i = 0; i < 4; i++) {
        int rr = bm + ty * 4 + i;
        int b2 = rr / 3136; int r2 = rr - b2 * 3136;
        int y2 = r2 / 56;   int x2 = r2 - y2 * 56;
        int wv = (y2 / 7) * 8 + (x2 / 7);
        int tk = (y2 % 7) * 7 + (x2 % 7);
        float4 v = make_float4(acc[i][0], acc[i][1], acc[i][2], acc[i][3]);
        *(float4*)(qbase + (((b2 * 6 + h) * 64 + wv) * 49 + tk) * 32 + d) = v;
    }
}

// ================= Kernel 2: per window-head attention =================
// blockIdx.x = (b*6+h)*64 + window
__global__ __launch_bounds__(256) void attn_kernel(const float* __restrict__ pe)
{
    __shared__ float Qs[49 * 33];
    __shared__ float Ks[49 * 33];
    __shared__ float Vs[49 * 33];
    __shared__ float S [49 * 50];
    __shared__ float PE[169];

    const int tid = threadIdx.x;
    const int bx  = blockIdx.x;
    const int wv  = bx & 63;
    const int wy  = wv >> 3, wx = wv & 7;

    const float* qg = g_qkv + (size_t)bx * 1568;
    const float* kg = qg + QT;
    const float* vg = qg + 2 * QT;

    for (int p = tid; p < 1568; p += 256) {
        int i = p >> 5, d = p & 31;
        Qs[i * 33 + d] = qg[p];
        Ks[i * 33 + d] = kg[p];
        Vs[i * 33 + d] = vg[p];
    }
    for (int p = tid; p < 169; p += 256) PE[p] = pe[p];
    __syncthreads();

    const float scale = 0.17677669529663687f;   // 32^-0.5
    const bool mrow = (wy == 7), mcol = (wx == 7);

    for (int p = tid; p < 2401; p += 256) {
        int i = p / 49, j = p - i * 49;
        const float* qr = Qs + i * 33;
        const float* kr = Ks + j * 33;
        float s = 0.f;
#pragma unroll
        for (int d = 0; d < 32; d++) s += qr[d] * kr[d];
        int iy = i / 7, ix = i - iy * 7;
        int jy = j / 7, jx = j - jy * 7;
        s = s * scale + PE[(jy - iy + 6) * 13 + (jx - ix + 6)];
        if (mrow && ((iy >= 4) != (jy >= 4))) s -= 1e9f;
        if (mcol && ((ix >= 4) != (jx >= 4))) s -= 1e9f;
        S[i * 50 + j] = s;
    }
    __syncthreads();

    const int lane = tid & 31, warp = tid >> 5;
    for (int i = warp; i < 49; i += 8) {
        float v0 = S[i * 50 + lane];
        float v1 = (lane < 17) ? S[i * 50 + lane + 32] : -3.4e38f;
        float m = fmaxf(v0, v1);
#pragma unroll
        for (int o = 16; o; o >>= 1) m = fmaxf(m, __shfl_xor_sync(0xffffffffu, m, o));
        float e0 = __expf(v0 - m);
        float e1 = (lane < 17) ? __expf(v1 - m) : 0.f;
        float sm = e0 + e1;
#pragma unroll
        for (int o = 16; o; o >>= 1) sm += __shfl_xor_sync(0xffffffffu, sm, o);
        float inv = 1.f / sm;
        S[i * 50 + lane] = e0 * inv;
        if (lane < 17) S[i * 50 + lane + 32] = e1 * inv;
    }
    __syncthreads();

    float* og = g_att + (size_t)bx * 1568;
    for (int p = tid; p < 1568; p += 256) {
        int i = p >> 5, d = p & 31;
        const float* sr = S + i * 50;
        const float* vr = Vs + d;
        float acc = 0.f;
#pragma unroll
        for (int j = 0; j < 49; j++) acc += sr[j] * vr[j * 33];
        og[p] = acc;
    }
}

// ================= Kernel 3: out-proj GEMM + inverse roll =================
__global__ __launch_bounds__(256) void proj_gemm(
    const float* __restrict__ wout, const float* __restrict__ bout,
    float* __restrict__ out)
{
    __shared__ float As[16 * 68];
    __shared__ float Bs[16 * 68];

    const int tid = threadIdx.x;
    const int bm  = blockIdx.x * 64;
    const int bn  = blockIdx.y * 64;
    const int tx  = tid & 15, ty = tid >> 4;

    // A gather from window layout
    const int am  = tid >> 2;
    const int ak  = (tid & 3) * 4;
    int row = bm + am;
    int b   = row / 3136; int r = row - b * 3136;
    int y   = r / 56;     int xx = r - y * 56;
    int wv  = (y / 7) * 8 + (xx / 7);
    int tk  = (y % 7) * 7 + (xx % 7);
    const float* abase = g_att + b * 602112 + wv * 1568 + tk * 32;  // + h*100352 + d

    const int bk  = tid >> 4;
    const int bn4 = (tid & 15) * 4;
    const float* bptr = wout + bk * 192 + bn + bn4;

    float acc[4][4] = {};

    for (int k0 = 0; k0 < 192; k0 += 16) {
        int k = k0 + ak;
        float4 av = *(const float4*)(abase + (k >> 5) * 100352 + (k & 31));
        float4 bv = *(const float4*)(bptr + k0 * 192);
        __syncthreads();
        As[(ak + 0) * 68 + am] = av.x;
        As[(ak + 1) * 68 + am] = av.y;
        As[(ak + 2) * 68 + am] = av.z;
        As[(ak + 3) * 68 + am] = av.w;
        *(float4*)(Bs + bk * 68 + bn4) = bv;
        __syncthreads();
#pragma unroll
        for (int kk = 0; kk < 16; kk++) {
            float4 a  = *(const float4*)(As + kk * 68 + ty * 4);
            float4 bb = *(const float4*)(Bs + kk * 68 + tx * 4);
            acc[0][0] += a.x * bb.x; acc[0][1] += a.x * bb.y;
            acc[0][2] += a.x * bb.z; acc[0][3] += a.x * bb.w;
            acc[1][0] += a.y * bb.x; acc[1][1] += a.y * bb.y;
            acc[1][2] += a.y * bb.z; acc[1][3] += a.y * bb.w;
            acc[2][0] += a.z * bb.x; acc[2][1] += a.z * bb.y;
            acc[2][2] += a.z * bb.z; acc[2][3] += a.z * bb.w;
            acc[3][0] += a.w * bb.x; acc[3][1] += a.w * bb.y;
            acc[3][2] += a.w * bb.z; acc[3][3] += a.w * bb.w;
        }
    }

    float4 bias = *(const float4*)(bout + bn + tx * 4);
#pragma unroll
    for (int i = 0; i < 4; i++) {
        int rr = bm + ty * 4 + i;
        int b2 = rr / 3136; int r2 = rr - b2 * 3136;
        int y2 = r2 / 56;   int x2 = r2 - y2 * 56;
        int yo = y2 + 3; if (yo >= 56) yo -= 56;   // inverse roll on write
        int xo = x2 + 3; if (xo >= 56) xo -= 56;
        float4 v = make_float4(acc[i][0] + bias.x, acc[i][1] + bias.y,
                               acc[i][2] + bias.z, acc[i][3] + bias.w);
        *(float4*)(out + ((b2 * 56 + yo) * 56 + xo) * 192 + bn + tx * 4) = v;
    }
}

// ================= launch =================
extern "C" void kernel_launch(void* const* d_in, const int* in_sizes, int n_in,
                              void* d_out, int out_size)
{
    const float* x    = (const float*)d_in[0];
    const float* wqkv = (const float*)d_in[1];
    const float* pe   = (const float*)d_in[2];
    const float* wout = (const float*)d_in[3];
    const float* bout = (const float*)d_in[4];
    float* out = (float*)d_out;

    dim3 g1(NTOK / 64, 9);     // 784 x 9
    qkv_gemm<<<g1, 256>>>(x, wqkv);

    attn_kernel<<<NB * HEADS * NW * NW, 256>>>(pe);   // 6144 blocks

    dim3 g3(NTOK / 64, 3);     // 784 x 3
    proj_gemm<<<g3, 256>>>(wout, bout, out);
}

// round 2
// speedup vs baseline: 2.0186x; 2.0186x over previous
#include <cuda_runtime.h>
#include <cstdint>

// ---------------- problem constants ----------------
#define QT (16*6*64*49*32)        // 9,633,792 floats per q/k/v tensor

__device__ float g_qkv[3u * QT];  // q | k | v in window layout [b,h,win,49,32]
__device__ float g_att[QT];       // attention output, same layout

// ---------------- helpers ----------------
__device__ __forceinline__ uint32_t f2tf(float f) {
    uint32_t u; asm("cvt.rna.tf32.f32 %0, %1;" : "=r"(u) : "f"(f)); return u;
}
__device__ __forceinline__ void mma8(float* c, const uint32_t* a, const uint32_t* b) {
    asm volatile("mma.sync.aligned.m16n8k8.row.col.f32.tf32.tf32.f32 "
        "{%0,%1,%2,%3}, {%4,%5,%6,%7}, {%8,%9}, {%0,%1,%2,%3};\n"
        : "+f"(c[0]), "+f"(c[1]), "+f"(c[2]), "+f"(c[3])
        : "r"(a[0]), "r"(a[1]), "r"(a[2]), "r"(a[3]), "r"(b[0]), "r"(b[1]));
}
__device__ __forceinline__ void st4tf(float* d, float4 v) {
    d[0] = __uint_as_float(f2tf(v.x));
    d[1] = __uint_as_float(f2tf(v.y));
    d[2] = __uint_as_float(f2tf(v.z));
    d[3] = __uint_as_float(f2tf(v.w));
}

// ================= Kernel 1: fused roll + QKV GEMM (tf32 MMA) =================
// Block tile 128(M) x 192(N), BK=16, 8 warps as 2(m) x 4(n), warp 64x48.
#define BM 128
#define BK 16
#define APAD 20
#define BPAD 200

__global__ __launch_bounds__(256) void qkv_gemm(
    const float* __restrict__ x, const float* __restrict__ wqkv)
{
    __shared__ __align__(16) float As[BM * APAD];   // [m][k]
    __shared__ __align__(16) float Bs[BK * BPAD];   // [k][n]

    const int tid  = threadIdx.x;
    const int warp = tid >> 5, lane = tid & 31;
    const int wm   = warp & 1, wn = warp >> 1;      // 2 x 4
    const int g    = lane >> 2, tg = lane & 3;
    const int bm   = blockIdx.x * BM;
    const int t    = blockIdx.y;                    // q/k/v selector (bn = t*192)

    // A global mapping (roll fused on read): 2 rows x float4 per thread
    const int ar0 = tid >> 2, ac = (tid & 3) * 4;
    const float* ap[2];
#pragma unroll
    for (int i = 0; i < 2; i++) {
        int row = bm + ar0 + i * 64;
        int b = row / 3136; int r = row - b * 3136;
        int y = r / 56, xx = r - y * 56;
        int ys = y + 3;  if (ys >= 56) ys -= 56;
        int xs = xx + 3; if (xs >= 56) xs -= 56;
        ap[i] = x + ((b * 56 + ys) * 56 + xs) * 192 + ac;
    }
    const int bkr = tid >> 4, bc = (tid & 15) * 4;
    const float* bp = wqkv + bkr * 576 + t * 192 + bc;

    float c[4][6][4] = {};
    float4 av[2], bv[3];
    av[0] = *(const float4*)(ap[0]);
    av[1] = *(const float4*)(ap[1]);
    bv[0] = *(const float4*)(bp);
    bv[1] = *(const float4*)(bp + 64);
    bv[2] = *(const float4*)(bp + 128);

#pragma unroll 1
    for (int it = 0; it < 12; it++) {
        __syncthreads();
        st4tf(As + ar0 * APAD + ac, av[0]);
        st4tf(As + (ar0 + 64) * APAD + ac, av[1]);
        st4tf(Bs + bkr * BPAD + bc, bv[0]);
        st4tf(Bs + bkr * BPAD + bc + 64, bv[1]);
        st4tf(Bs + bkr * BPAD + bc + 128, bv[2]);
        __syncthreads();
        if (it < 11) {
            int k0 = (it + 1) * 16;
            av[0] = *(const float4*)(ap[0] + k0);
            av[1] = *(const float4*)(ap[1] + k0);
            bv[0] = *(const float4*)(bp + k0 * 576);
            bv[1] = *(const float4*)(bp + k0 * 576 + 64);
            bv[2] = *(const float4*)(bp + k0 * 576 + 128);
        }
#pragma unroll
        for (int kk = 0; kk < 16; kk += 8) {
            uint32_t af[4][4], bf[6][2];
#pragma unroll
            for (int mi = 0; mi < 4; mi++) {
                int rb = wm * 64 + mi * 16 + g;
                af[mi][0] = __float_as_uint(As[rb * APAD + kk + tg]);
                af[mi][1] = __float_as_uint(As[(rb + 8) * APAD + kk + tg]);
                af[mi][2] = __float_as_uint(As[rb * APAD + kk + tg + 4]);
                af[mi][3] = __float_as_uint(As[(rb + 8) * APAD + kk + tg + 4]);
            }
#pragma unroll
            for (int ni = 0; ni < 6; ni++) {
                int nn = wn * 48 + ni * 8 + g;
                bf[ni][0] = __float_as_uint(Bs[(kk + tg) * BPAD + nn]);
                bf[ni][1] = __float_as_uint(Bs[(kk + tg + 4) * BPAD + nn]);
            }
#pragma unroll
            for (int mi = 0; mi < 4; mi++)
#pragma unroll
                for (int ni = 0; ni < 6; ni++)
                    mma8(c[mi][ni], af[mi], bf[ni]);
        }
    }

    // epilogue: scatter into window layout [b,h,win,49,32]
    float* qb = g_qkv + (size_t)t * QT;
#pragma unroll
    for (int mi = 0; mi < 4; mi++) {
#pragma unroll
        for (int half = 0; half < 2; half++) {
            int r = bm + wm * 64 + mi * 16 + g + half * 8;
            int b = r / 3136; int rr = r - b * 3136;
            int y = rr / 56, xx = rr - y * 56;
            int wv = (y / 7) * 8 + (xx / 7);
            int tk = (y % 7) * 7 + (xx % 7);
            int base = b * 602112 + wv * 1568 + tk * 32;
#pragma unroll
            for (int ni = 0; ni < 6; ni++) {
                int cp = wn * 48 + ni * 8 + tg * 2;
                int h = cp >> 5, d = cp & 31;
                float2 v = make_float2(c[mi][ni][half * 2], c[mi][ni][half * 2 + 1]);
                *(float2*)(qb + base + h * 100352 + d) = v;
            }
        }
    }
}

// ================= Kernel 2: per window-head attention =================
__global__ __launch_bounds__(256) void attn_kernel(const float* __restrict__ pe)
{
    __shared__ float Qs[52 * 33];
    __shared__ float Ks[52 * 33];
    __shared__ __align__(16) float Vs[49 * 36];
    __shared__ float S [49 * 50];
    __shared__ float PE[169];

    const int tid = threadIdx.x;
    const int bx  = blockIdx.x;
    const int wv  = bx & 63;
    const int wy  = wv >> 3, wx = wv & 7;

    const float* qg = g_qkv + (size_t)bx * 1568;
    const float* kg = qg + QT;
    const float* vg = qg + 2 * QT;

    if (tid < 99) { Qs[49 * 33 + tid] = 0.f; Ks[49 * 33 + tid] = 0.f; }
    for (int p = tid; p < 1568; p += 256) {
        int i = p >> 5, d = p & 31;
        Qs[i * 33 + d] = qg[p];
        Ks[i * 33 + d] = kg[p];
        Vs[i * 36 + d] = vg[p];
    }
    for (int p = tid; p < 169; p += 256) PE[p] = pe[p];
    __syncthreads();

    const float scale = 0.17677669529663687f;
    const bool mrow = (wy == 7), mcol = (wx == 7);

    // QK^T: 4x4 register tile per thread (169 active threads)
    if (tid < 169) {
        const int i0 = (tid / 13) * 4, j0 = (tid % 13) * 4;
        float s[4][4] = {};
#pragma unroll 4
        for (int d = 0; d < 32; d++) {
            float q0 = Qs[(i0 + 0) * 33 + d];
            float q1 = Qs[(i0 + 1) * 33 + d];
            float q2 = Qs[(i0 + 2) * 33 + d];
            float q3 = Qs[(i0 + 3) * 33 + d];
            float k0 = Ks[(j0 + 0) * 33 + d];
            float k1 = Ks[(j0 + 1) * 33 + d];
            float k2 = Ks[(j0 + 2) * 33 + d];
            float k3 = Ks[(j0 + 3) * 33 + d];
            s[0][0] += q0 * k0; s[0][1] += q0 * k1; s[0][2] += q0 * k2; s[0][3] += q0 * k3;
            s[1][0] += q1 * k0; s[1][1] += q1 * k1; s[1][2] += q1 * k2; s[1][3] += q1 * k3;
            s[2][0] += q2 * k0; s[2][1] += q2 * k1; s[2][2] += q2 * k2; s[2][3] += q2 * k3;
            s[3][0] += q3 * k0; s[3][1] += q3 * k1; s[3][2] += q3 * k2; s[3][3] += q3 * k3;
        }
#pragma unroll
        for (int ii = 0; ii < 4; ii++) {
            int i = i0 + ii;
            if (i >= 49) break;
            int iy = i / 7, ix = i - iy * 7;
#pragma unroll
            for (int jj = 0; jj < 4; jj++) {
                int j = j0 + jj;
                if (j >= 49) break;
                int jy = j / 7, jx = j - jy * 7;
                float v = s[ii][jj] * scale + PE[(jy - iy + 6) * 13 + (jx - ix + 6)];
                if (mrow && ((iy >= 4) != (jy >= 4))) v -= 1e9f;
                if (mcol && ((ix >= 4) != (jx >= 4))) v -= 1e9f;
                S[i * 50 + j] = v;
            }
        }
    }
    __syncthreads();

    // softmax: warp per row
    const int lane = tid & 31, warp = tid >> 5;
    for (int i = warp; i < 49; i += 8) {
        float v0 = S[i * 50 + lane];
        float v1 = (lane < 17) ? S[i * 50 + lane + 32] : -3.4e38f;
        float m = fmaxf(v0, v1);
#pragma unroll
        for (int o = 16; o; o >>= 1) m = fmaxf(m, __shfl_xor_sync(0xffffffffu, m, o));
        float e0 = __expf(v0 - m);
        float e1 = (lane < 17) ? __expf(v1 - m) : 0.f;
        float sm = e0 + e1;
#pragma unroll
        for (int o = 16; o; o >>= 1) sm += __shfl_xor_sync(0xffffffffu, sm, o);
        float inv = 1.f / sm;
        S[i * 50 + lane] = e0 * inv;
        if (lane < 17) S[i * 50 + lane + 32] = e1 * inv;
    }
    __syncthreads();

    // P @ V: float4 over d
    float* og = g_att + (size_t)bx * 1568;
    for (int p = tid; p < 392; p += 256) {
        int i = p >> 3, d = (p & 7) * 4;
        const float* sr = S + i * 50;
        float4 acc = make_float4(0.f, 0.f, 0.f, 0.f);
#pragma unroll 7
        for (int j = 0; j < 49; j++) {
            float s_ = sr[j];
            float4 v = *(const float4*)(Vs + j * 36 + d);
            acc.x += s_ * v.x; acc.y += s_ * v.y;
            acc.z += s_ * v.z; acc.w += s_ * v.w;
        }
        *(float4*)(og + (i << 5) + d) = acc;
    }
}

// ================= Kernel 3: out-proj GEMM (tf32 MMA) + inverse roll =================
__global__ __launch_bounds__(256) void proj_gemm(
    const float* __restrict__ wout, const float* __restrict__ bout,
    float* __restrict__ out)
{
    __shared__ __align__(16) float As[BM * APAD];
    __shared__ __align__(16) float Bs[BK * BPAD];

    const int tid  = threadIdx.x;
    const int warp = tid >> 5, lane = tid & 31;
    const int wm   = warp & 1, wn = warp >> 1;
    const int g    = lane >> 2, tg = lane & 3;
    const int bm   = blockIdx.x * BM;

    const int ar0 = tid >> 2, ac = (tid & 3) * 4;
    const float* ab[2];
#pragma unroll
    for (int i = 0; i < 2; i++) {
        int row = bm + ar0 + i * 64;
        int b = row / 3136; int r = row - b * 3136;
        int y = r / 56, xx = r - y * 56;
        int wv = (y / 7) * 8 + (xx / 7);
        int tk = (y % 7) * 7 + (xx % 7);
        ab[i] = g_att + b * 602112 + wv * 1568 + tk * 32;
    }
    const int bkr = tid >> 4, bc = (tid & 15) * 4;
    const float* bp = wout + bkr * 192 + bc;

    float c[4][6][4] = {};
    float4 av[2], bv[3];
    {
        int k = ac;
        av[0] = *(const float4*)(ab[0] + (k >> 5) * 100352 + (k & 31));
        av[1] = *(const float4*)(ab[1] + (k >> 5) * 100352 + (k & 31));
        bv[0] = *(const float4*)(bp);
        bv[1] = *(const float4*)(bp + 64);
        bv[2] = *(const float4*)(bp + 128);
    }

#pragma unroll 1
    for (int it = 0; it < 12; it++) {
        __syncthreads();
        st4tf(As + ar0 * APAD + ac, av[0]);
        st4tf(As + (ar0 + 64) * APAD + ac, av[1]);
        st4tf(Bs + bkr * BPAD + bc, bv[0]);
        st4tf(Bs + bkr * BPAD + bc + 64, bv[1]);
        st4tf(Bs + bkr * BPAD + bc + 128, bv[2]);
        __syncthreads();
        if (it < 11) {
            int k = (it + 1) * 16 + ac;
            av[0] = *(const float4*)(ab[0] + (k >> 5) * 100352 + (k & 31));
            av[1] = *(const float4*)(ab[1] + (k >> 5) * 100352 + (k & 31));
            bv[0] = *(const float4*)(bp + (it + 1) * 16 * 192);
            bv[1] = *(const float4*)(bp + (it + 1) * 16 * 192 + 64);
            bv[2] = *(const float4*)(bp + (it + 1) * 16 * 192 + 128);
        }
#pragma unroll
        for (int kk = 0; kk < 16; kk += 8) {
            uint32_t af[4][4], bf[6][2];
#pragma unroll
            for (int mi = 0; mi < 4; mi++) {
                int rb = wm * 64 + mi * 16 + g;
                af[mi][0] = __float_as_uint(As[rb * APAD + kk + tg]);
                af[mi][1] = __float_as_uint(As[(rb + 8) * APAD + kk + tg]);
                af[mi][2] = __float_as_uint(As[rb * APAD + kk + tg + 4]);
                af[mi][3] = __float_as_uint(As[(rb + 8) * APAD + kk + tg + 4]);
            }
#pragma unroll
            for (int ni = 0; ni < 6; ni++) {
                int nn = wn * 48 + ni * 8 + g;
                bf[ni][0] = __float_as_uint(Bs[(kk + tg) * BPAD + nn]);
                bf[ni][1] = __float_as_uint(Bs[(kk + tg + 4) * BPAD + nn]);
            }
#pragma unroll
            for (int mi = 0; mi < 4; mi++)
#pragma unroll
                for (int ni = 0; ni < 6; ni++)
                    mma8(c[mi][ni], af[mi], bf[ni]);
        }
    }

    // epilogue: bias + inverse roll
#pragma unroll
    for (int mi = 0; mi < 4; mi++) {
#pragma unroll
        for (int half = 0; half < 2; half++) {
            int r = bm + wm * 64 + mi * 16 + g + half * 8;
            int b = r / 3136; int rr = r - b * 3136;
            int y = rr / 56, xx = rr - y * 56;
            int yo = y + 3;  if (yo >= 56) yo -= 56;
            int xo = xx + 3; if (xo >= 56) xo -= 56;
            float* op = out + ((b * 56 + yo) * 56 + xo) * 192;
#pragma unroll
            for (int ni = 0; ni < 6; ni++) {
                int cp = wn * 48 + ni * 8 + tg * 2;
                float2 bb = *(const float2*)(bout + cp);
                float2 v = make_float2(c[mi][ni][half * 2] + bb.x,
                                       c[mi][ni][half * 2 + 1] + bb.y);
                *(float2*)(op + cp) = v;
            }
        }
    }
}

// ================= launch =================
extern "C" void kernel_launch(void* const* d_in, const int* in_sizes, int n_in,
                              void* d_out, int out_size)
{
    const float* x    = (const float*)d_in[0];
    const float* wqkv = (const float*)d_in[1];
    const float* pe   = (const float*)d_in[2];
    const float* wout = (const float*)d_in[3];
    const float* bout = (const float*)d_in[4];
    float* out = (float*)d_out;

    dim3 g1(392, 3);
    qkv_gemm<<<g1, 256>>>(x, wqkv);

    attn_kernel<<<16 * 6 * 64, 256>>>(pe);

    proj_gemm<<<392, 256>>>(wout, bout, out);
}

// round 3
// speedup vs baseline: 2.1117x; 1.0461x over previous
#include <cuda_runtime.h>
#include <cstdint>

#define QT (16*6*64*49*32)        // 9,633,792 floats per q/k/v tensor

__device__ float g_qkv[3u * QT];  // q | k | v in window layout [b,h,win,49,32]
__device__ float g_att[QT];       // attention output, same layout

// ---------------- helpers ----------------
__device__ __forceinline__ uint32_t f2tf(float f) {
    uint32_t u; asm("cvt.rna.tf32.f32 %0, %1;" : "=r"(u) : "f"(f)); return u;
}
__device__ __forceinline__ void mma8(float* c, const uint32_t* a, const uint32_t* b) {
    asm volatile("mma.sync.aligned.m16n8k8.row.col.f32.tf32.tf32.f32 "
        "{%0,%1,%2,%3}, {%4,%5,%6,%7}, {%8,%9}, {%0,%1,%2,%3};\n"
        : "+f"(c[0]), "+f"(c[1]), "+f"(c[2]), "+f"(c[3])
        : "r"(a[0]), "r"(a[1]), "r"(a[2]), "r"(a[3]), "r"(b[0]), "r"(b[1]));
}
__device__ __forceinline__ void cpa16(void* s, const void* g) {
    uint32_t sa = (uint32_t)__cvta_generic_to_shared(s);
    asm volatile("cp.async.cg.shared.global [%0], [%1], 16;" :: "r"(sa), "l"(g));
}
#define CP_COMMIT() asm volatile("cp.async.commit_group;")
#define CP_WAIT1()  asm volatile("cp.async.wait_group 1;")
#define CP_WAIT0()  asm volatile("cp.async.wait_group 0;")

// ============ GEMM config: BM=128, BN=96, BK=16, 128 threads (4 warps 2x2) ============
#define ASTR 20
#define BSTR 104

// ================= Kernel 1: fused roll + QKV GEMM (tf32 MMA, cp.async) =================
__global__ __launch_bounds__(128, 3) void qkv_gemm(
    const float* __restrict__ x, const float* __restrict__ wqkv)
{
    __shared__ __align__(16) float As[2][128 * ASTR];
    __shared__ __align__(16) float Bs[2][16 * BSTR];

    const int tid  = threadIdx.x;
    const int warp = tid >> 5, lane = tid & 31;
    const int wm   = warp & 1, wn = warp >> 1;          // 2 x 2
    const int g    = lane >> 2, tg = lane & 3;
    const int bm   = blockIdx.x * 128;
    const int nb   = blockIdx.y;                        // 0..5, 96 cols each

    // A: one row per thread, roll fused on read
    const float* aptr;
    {
        int row = bm + tid;
        int b = row / 3136; int r = row - b * 3136;
        int y = r / 56, xx = r - y * 56;
        int ys = y + 3;  if (ys >= 56) ys -= 56;
        int xs = xx + 3; if (xs >= 56) xs -= 56;
        aptr = x + ((b * 56 + ys) * 56 + xs) * 192;
    }
    // B: thread -> (k-row, 3 chunks of 16B)
    const int bkr = tid >> 3, bcg = (tid & 7) * 4;
    const float* bptr = wqkv + bkr * 576 + nb * 96 + bcg;

    float c[4][6][4] = {};

    // prologue: tile 0
    {
        float* ad = As[0] + tid * ASTR;
        cpa16(ad + 0,  aptr + 0);  cpa16(ad + 4,  aptr + 4);
        cpa16(ad + 8,  aptr + 8);  cpa16(ad + 12, aptr + 12);
        float* bd = Bs[0] + bkr * BSTR + bcg;
        cpa16(bd + 0,  bptr + 0);  cpa16(bd + 32, bptr + 32);  cpa16(bd + 64, bptr + 64);
        CP_COMMIT();
    }

#pragma unroll 1
    for (int it = 0; it < 12; it++) {
        if (it < 11) {
            int k0 = (it + 1) * 16;
            float* ad = As[(it + 1) & 1] + tid * ASTR;
            cpa16(ad + 0,  aptr + k0 + 0);  cpa16(ad + 4,  aptr + k0 + 4);
            cpa16(ad + 8,  aptr + k0 + 8);  cpa16(ad + 12, aptr + k0 + 12);
            float* bd = Bs[(it + 1) & 1] + bkr * BSTR + bcg;
            const float* bs = bptr + k0 * 576;
            cpa16(bd + 0, bs + 0);  cpa16(bd + 32, bs + 32);  cpa16(bd + 64, bs + 64);
            CP_COMMIT();
            CP_WAIT1();
        } else {
            CP_WAIT0();
        }
        __syncthreads();

        const float* Ab = As[it & 1];
        const float* Bb = Bs[it & 1];
#pragma unroll
        for (int kk = 0; kk < 16; kk += 8) {
            uint32_t af[4][4], bf[6][2];
#pragma unroll
            for (int mi = 0; mi < 4; mi++) {
                int rb = wm * 64 + mi * 16 + g;
                af[mi][0] = f2tf(Ab[rb * ASTR + kk + tg]);
                af[mi][1] = f2tf(Ab[(rb + 8) * ASTR + kk + tg]);
                af[mi][2] = f2tf(Ab[rb * ASTR + kk + tg + 4]);
                af[mi][3] = f2tf(Ab[(rb + 8) * ASTR + kk + tg + 4]);
            }
#pragma unroll
            for (int ni = 0; ni < 6; ni++) {
                int nn = wn * 48 + ni * 8 + g;
                bf[ni][0] = f2tf(Bb[(kk + tg) * BSTR + nn]);
                bf[ni][1] = f2tf(Bb[(kk + tg + 4) * BSTR + nn]);
            }
#pragma unroll
            for (int mi = 0; mi < 4; mi++)
#pragma unroll
                for (int ni = 0; ni < 6; ni++)
                    mma8(c[mi][ni], af[mi], bf[ni]);
        }
        __syncthreads();
    }

    // epilogue: scatter into window layout [b,h,win,49,32]
    const int t = nb >> 1;                    // q/k/v selector
    float* qb = g_qkv + (size_t)t * QT;
#pragma unroll
    for (int mi = 0; mi < 4; mi++) {
#pragma unroll
        for (int half = 0; half < 2; half++) {
            int r = bm + wm * 64 + mi * 16 + g + half * 8;
            int b = r / 3136; int rr = r - b * 3136;
            int y = rr / 56, xx = rr - y * 56;
            int wv = (y / 7) * 8 + (xx / 7);
            int tk = (y % 7) * 7 + (xx % 7);
            int base = b * 602112 + wv * 1568 + tk * 32;
#pragma unroll
            for (int ni = 0; ni < 6; ni++) {
                int cp = nb * 96 + wn * 48 + ni * 8 + tg * 2;
                int cc = cp - t * 192;
                int h = cc >> 5, d = cc & 31;
                float2 v = make_float2(c[mi][ni][half * 2], c[mi][ni][half * 2 + 1]);
                *(float2*)(qb + base + h * 100352 + d) = v;
            }
        }
    }
}

// ================= Kernel 2: per window-head attention =================
__global__ __launch_bounds__(256) void attn_kernel(const float* __restrict__ pe)
{
    __shared__ float Qs[52 * 33];
    __shared__ float Ks[52 * 33];
    __shared__ __align__(16) float Vs[49 * 36];
    __shared__ float S [49 * 50];
    __shared__ float PE[169];

    const int tid = threadIdx.x;
    const int bx  = blockIdx.x;
    const int wv  = bx & 63;
    const int wy  = wv >> 3, wx = wv & 7;

    const float* qg = g_qkv + (size_t)bx * 1568;
    const float* kg = qg + QT;
    const float* vg = qg + 2 * QT;

    if (tid < 99) { Qs[49 * 33 + tid] = 0.f; Ks[49 * 33 + tid] = 0.f; }
    for (int p = tid; p < 1568; p += 256) {
        int i = p >> 5, d = p & 31;
        Qs[i * 33 + d] = qg[p];
        Ks[i * 33 + d] = kg[p];
        Vs[i * 36 + d] = vg[p];
    }
    for (int p = tid; p < 169; p += 256) PE[p] = pe[p];
    __syncthreads();

    const float scale = 0.17677669529663687f;
    const bool mrow = (wy == 7), mcol = (wx == 7);

    // QK^T: 4x4 register tile per thread (169 active threads)
    if (tid < 169) {
        const int i0 = (tid / 13) * 4, j0 = (tid % 13) * 4;
        float s[4][4] = {};
#pragma unroll 4
        for (int d = 0; d < 32; d++) {
            float q0 = Qs[(i0 + 0) * 33 + d];
            float q1 = Qs[(i0 + 1) * 33 + d];
            float q2 = Qs[(i0 + 2) * 33 + d];
            float q3 = Qs[(i0 + 3) * 33 + d];
            float k0 = Ks[(j0 + 0) * 33 + d];
            float k1 = Ks[(j0 + 1) * 33 + d];
            float k2 = Ks[(j0 + 2) * 33 + d];
            float k3 = Ks[(j0 + 3) * 33 + d];
            s[0][0] += q0 * k0; s[0][1] += q0 * k1; s[0][2] += q0 * k2; s[0][3] += q0 * k3;
            s[1][0] += q1 * k0; s[1][1] += q1 * k1; s[1][2] += q1 * k2; s[1][3] += q1 * k3;
            s[2][0] += q2 * k0; s[2][1] += q2 * k1; s[2][2] += q2 * k2; s[2][3] += q2 * k3;
            s[3][0] += q3 * k0; s[3][1] += q3 * k1; s[3][2] += q3 * k2; s[3][3] += q3 * k3;
        }
#pragma unroll
        for (int ii = 0; ii < 4; ii++) {
            int i = i0 + ii;
            if (i >= 49) break;
            int iy = i / 7, ix = i - iy * 7;
#pragma unroll
            for (int jj = 0; jj < 4; jj++) {
                int j = j0 + jj;
                if (j >= 49) break;
                int jy = j / 7, jx = j - jy * 7;
                float v = s[ii][jj] * scale + PE[(jy - iy + 6) * 13 + (jx - ix + 6)];
                if (mrow && ((iy >= 4) != (jy >= 4))) v -= 1e9f;
                if (mcol && ((ix >= 4) != (jx >= 4))) v -= 1e9f;
                S[i * 50 + j] = v;
            }
        }
    }
    __syncthreads();

    // softmax: warp per row
    const int lane = tid & 31, warp = tid >> 5;
    for (int i = warp; i < 49; i += 8) {
        float v0 = S[i * 50 + lane];
        float v1 = (lane < 17) ? S[i * 50 + lane + 32] : -3.4e38f;
        float m = fmaxf(v0, v1);
#pragma unroll
        for (int o = 16; o; o >>= 1) m = fmaxf(m, __shfl_xor_sync(0xffffffffu, m, o));
        float e0 = __expf(v0 - m);
        float e1 = (lane < 17) ? __expf(v1 - m) : 0.f;
        float sm = e0 + e1;
#pragma unroll
        for (int o = 16; o; o >>= 1) sm += __shfl_xor_sync(0xffffffffu, sm, o);
        float inv = 1.f / sm;
        S[i * 50 + lane] = e0 * inv;
        if (lane < 17) S[i * 50 + lane + 32] = e1 * inv;
    }
    __syncthreads();

    // P @ V: thread tile = 2 rows(i) x 4 cols(d); 200 active threads
    float* og = g_att + (size_t)bx * 1568;
    if (tid < 200) {
        const int ig = tid >> 3, dg = (tid & 7) * 4;
        const int i0 = ig * 2;
        const bool two = (i0 + 1 < 49);
        float4 a0 = make_float4(0.f, 0.f, 0.f, 0.f);
        float4 a1 = make_float4(0.f, 0.f, 0.f, 0.f);
        const float* s0 = S + i0 * 50;
        const float* s1 = s0 + 50;
#pragma unroll 7
        for (int j = 0; j < 49; j++) {
            float4 v = *(const float4*)(Vs + j * 36 + dg);
            float p0 = s0[j];
            a0.x += p0 * v.x; a0.y += p0 * v.y; a0.z += p0 * v.z; a0.w += p0 * v.w;
            if (two) {
                float p1 = s1[j];
                a1.x += p1 * v.x; a1.y += p1 * v.y; a1.z += p1 * v.z; a1.w += p1 * v.w;
            }
        }
        *(float4*)(og + (i0 << 5) + dg) = a0;
        if (two) *(float4*)(og + ((i0 + 1) << 5) + dg) = a1;
    }
}

// ================= Kernel 3: out-proj GEMM (tf32 MMA, cp.async) + inverse roll =================
__global__ __launch_bounds__(128, 3) void proj_gemm(
    const float* __restrict__ wout, const float* __restrict__ bout,
    float* __restrict__ out)
{
    __shared__ __align__(16) float As[2][128 * ASTR];
    __shared__ __align__(16) float Bs[2][16 * BSTR];

    const int tid  = threadIdx.x;
    const int warp = tid >> 5, lane = tid & 31;
    const int wm   = warp & 1, wn = warp >> 1;
    const int g    = lane >> 2, tg = lane & 3;
    const int bm   = blockIdx.x * 128;
    const int nb   = blockIdx.y;                 // 0..1

    // A: one row per thread, gathered from window layout
    const float* abase;
    {
        int row = bm + tid;
        int b = row / 3136; int r = row - b * 3136;
        int y = r / 56, xx = r - y * 56;
        int wv = (y / 7) * 8 + (xx / 7);
        int tk = (y % 7) * 7 + (xx % 7);
        abase = g_att + b * 602112 + wv * 1568 + tk * 32;  // + h*100352 + d
    }
    const int bkr = tid >> 3, bcg = (tid & 7) * 4;
    const float* bptr = wout + bkr * 192 + nb * 96 + bcg;

    float c[4][6][4] = {};

    {
        float* ad = As[0] + tid * ASTR;
        cpa16(ad + 0,  abase + 0);  cpa16(ad + 4,  abase + 4);
        cpa16(ad + 8,  abase + 8);  cpa16(ad + 12, abase + 12);
        float* bd = Bs[0] + bkr * BSTR + bcg;
        cpa16(bd + 0, bptr + 0);  cpa16(bd + 32, bptr + 32);  cpa16(bd + 64, bptr + 64);
        CP_COMMIT();
    }

#pragma unroll 1
    for (int it = 0; it < 12; it++) {
        if (it < 11) {
            int itn = it + 1;
            const float* as = abase + (itn >> 1) * 100352 + (itn & 1) * 16;
            float* ad = As[itn & 1] + tid * ASTR;
            cpa16(ad + 0,  as + 0);  cpa16(ad + 4,  as + 4);
            cpa16(ad + 8,  as + 8);  cpa16(ad + 12, as + 12);
            float* bd = Bs[itn & 1] + bkr * BSTR + bcg;
            const float* bs = bptr + itn * 16 * 192;
            cpa16(bd + 0, bs + 0);  cpa16(bd + 32, bs + 32);  cpa16(bd + 64, bs + 64);
            CP_COMMIT();
            CP_WAIT1();
        } else {
            CP_WAIT0();
        }
        __syncthreads();

        const float* Ab = As[it & 1];
        const float* Bb = Bs[it & 1];
#pragma unroll
        for (int kk = 0; kk < 16; kk += 8) {
            uint32_t af[4][4], bf[6][2];
#pragma unroll
            for (int mi = 0; mi < 4; mi++) {
                int rb = wm * 64 + mi * 16 + g;
                af[mi][0] = f2tf(Ab[rb * ASTR + kk + tg]);
                af[mi][1] = f2tf(Ab[(rb + 8) * ASTR + kk + tg]);
                af[mi][2] = f2tf(Ab[rb * ASTR + kk + tg + 4]);
                af[mi][3] = f2tf(Ab[(rb + 8) * ASTR + kk + tg + 4]);
            }
#pragma unroll
            for (int ni = 0; ni < 6; ni++) {
                int nn = wn * 48 + ni * 8 + g;
                bf[ni][0] = f2tf(Bb[(kk + tg) * BSTR + nn]);
                bf[ni][1] = f2tf(Bb[(kk + tg + 4) * BSTR + nn]);
            }
#pragma unroll
            for (int mi = 0; mi < 4; mi++)
#pragma unroll
                for (int ni = 0; ni < 6; ni++)
                    mma8(c[mi][ni], af[mi], bf[ni]);
        }
        __syncthreads();
    }

    // epilogue: bias + inverse roll
#pragma unroll
    for (int mi = 0; mi < 4; mi++) {
#pragma unroll
        for (int half = 0; half < 2; half++) {
            int r = bm + wm * 64 + mi * 16 + g + half * 8;
            int b = r / 3136; int rr = r - b * 3136;
            int y = rr / 56, xx = rr - y * 56;
            int yo = y + 3;  if (yo >= 56) yo -= 56;
            int xo = xx + 3; if (xo >= 56) xo -= 56;
            float* op = out + ((b * 56 + yo) * 56 + xo) * 192;
#pragma unroll
            for (int ni = 0; ni < 6; ni++) {
                int cp = nb * 96 + wn * 48 + ni * 8 + tg * 2;
                float2 bb = *(const float2*)(bout + cp);
                float2 v = make_float2(c[mi][ni][half * 2] + bb.x,
                                       c[mi][ni][half * 2 + 1] + bb.y);
                *(float2*)(op + cp) = v;
            }
        }
    }
}

// ================= launch =================
extern "C" void kernel_launch(void* const* d_in, const int* in_sizes, int n_in,
                              void* d_out, int out_size)
{
    const float* x    = (const float*)d_in[0];
    const float* wqkv = (const float*)d_in[1];
    const float* pe   = (const float*)d_in[2];
    const float* wout = (const float*)d_in[3];
    const float* bout = (const float*)d_in[4];
    float* out = (float*)d_out;

    dim3 g1(392, 6);
    qkv_gemm<<<g1, 128>>>(x, wqkv);

    attn_kernel<<<16 * 6 * 64, 256>>>(pe);

    dim3 g3(392, 2);
    proj_gemm<<<g3, 128>>>(wout, bout, out);
}

// round 5
// speedup vs baseline: 2.6527x; 1.2562x over previous
#include <cuda_runtime.h>
#include <cuda_fp16.h>
#include <cstdint>

#define QT (16*6*64*49*32)            // 9,633,792 elements per q/k/v tensor

__device__ __half g_xh[50176 * 192];  // rolled x, fp16, token-major
__device__ __half g_wh[576 * 192];    // wqkv^T [n][k] fp16
__device__ __half g_woh[192 * 192];   // wout^T [n][k] fp16
__device__ __half g_qkvh[3u * QT];    // q|k|v fp16, window layout [b,h,win,49,32]
__device__ __half g_atth[QT];         // attention out fp16, window layout

// ---------------- helpers ----------------
__device__ __forceinline__ void mma16(float* c, const uint32_t* a, const uint32_t* b) {
    asm volatile("mma.sync.aligned.m16n8k16.row.col.f32.f16.f16.f32 "
        "{%0,%1,%2,%3}, {%4,%5,%6,%7}, {%8,%9}, {%0,%1,%2,%3};\n"
        : "+f"(c[0]), "+f"(c[1]), "+f"(c[2]), "+f"(c[3])
        : "r"(a[0]), "r"(a[1]), "r"(a[2]), "r"(a[3]), "r"(b[0]), "r"(b[1]));
}
__device__ __forceinline__ void cpa16(uint32_t s, const void* g) {
    asm volatile("cp.async.cg.shared.global [%0], [%1], 16;" :: "r"(s), "l"(g));
}
#define CP_COMMIT() asm volatile("cp.async.commit_group;")
#define CP_WAIT1()  asm volatile("cp.async.wait_group 1;")
#define CP_WAIT0()  asm volatile("cp.async.wait_group 0;")
__device__ __forceinline__ uint32_t smem_u32(const void* p) {
    uint32_t a;
    asm("{ .reg .u64 t; cvta.to.shared.u64 t, %1; cvt.u32.u64 %0, t; }" : "=r"(a) : "l"(p));
    return a;
}

// ================= prep kernels =================
__global__ __launch_bounds__(256) void prep_x(const float* __restrict__ x) {
    int i = blockIdx.x * 256 + threadIdx.x;      // 2,408,448 (groups of 4)
    int e = i * 4;
    int t = e / 192, c = e - t * 192;
    int b = t / 3136; int r = t - b * 3136;
    int y = r / 56, xx = r - y * 56;
    int ys = y + 3;  if (ys >= 56) ys -= 56;     // roll fused here
    int xs = xx + 3; if (xs >= 56) xs -= 56;
    float4 v = *(const float4*)(x + ((b * 56 + ys) * 56 + xs) * 192 + c);
    __half2 h0 = __floats2half2_rn(v.x, v.y);
    __half2 h1 = __floats2half2_rn(v.z, v.w);
    *(__half2*)(g_xh + e) = h0;
    *(__half2*)(g_xh + e + 2) = h1;
}
__global__ __launch_bounds__(256) void prep_w(const float* __restrict__ w) {
    int i = blockIdx.x * 256 + threadIdx.x;      // 27648
    int e = i * 4;
    int n = e / 192, k = e - n * 192;
#pragma unroll
    for (int j = 0; j < 4; j++)
        g_wh[e + j] = __float2half_rn(w[(k + j) * 576 + n]);
}
__global__ __launch_bounds__(256) void prep_wo(const float* __restrict__ w) {
    int i = blockIdx.x * 256 + threadIdx.x;      // 9216
    int e = i * 4;
    int n = e / 192, k = e - n * 192;
#pragma unroll
    for (int j = 0; j < 4; j++)
        g_woh[e + j] = __float2half_rn(w[(k + j) * 192 + n]);
}

// ============ fp16 GEMM: BM=128, BN=96, BK=32, 128 threads (4 warps 2x2) ============
#define LDA 40   // halves; words 20g+tg distinct mod 32 -> conflict-free

// ================= Kernel 1: QKV GEMM =================
__global__ __launch_bounds__(128, 3) void qkv_gemm(void)
{
    __shared__ __align__(16) __half As[2][128 * LDA];
    __shared__ __align__(16) __half Bs[2][96 * LDA];

    const int tid  = threadIdx.x;
    const int warp = tid >> 5, lane = tid & 31;
    const int wm   = warp & 1, wn = warp >> 1;          // 2 x 2
    const int g    = lane >> 2, tg = lane & 3;
    const int bm   = blockIdx.x * 128;
    const int nb   = blockIdx.y;                        // 0..5

    const __half* ap = g_xh + (size_t)(bm + tid) * 192; // 1 row per thread
    const int bn = tid >> 2, bq = tid & 3;              // B: rows tid>>2 (+32,+64)

    uint32_t a_s[2], b_s[2];
    a_s[0] = smem_u32(As[0]); a_s[1] = smem_u32(As[1]);
    b_s[0] = smem_u32(Bs[0]); b_s[1] = smem_u32(Bs[1]);

#define LD_CHUNK(cc, ss) do { \
        uint32_t ad = a_s[ss] + (uint32_t)(tid * LDA) * 2; \
        const __half* asrc = ap + (cc) * 32; \
        cpa16(ad + 0,  asrc + 0);  cpa16(ad + 16, asrc + 8); \
        cpa16(ad + 32, asrc + 16); cpa16(ad + 48, asrc + 24); \
        _Pragma("unroll") \
        for (int ii = 0; ii < 3; ii++) { \
            int n = bn + ii * 32; \
            cpa16(b_s[ss] + (uint32_t)(n * LDA + bq * 8) * 2, \
                  g_wh + (size_t)(nb * 96 + n) * 192 + (cc) * 32 + bq * 8); \
        } \
        CP_COMMIT(); } while (0)

    float c[4][6][4] = {};
    LD_CHUNK(0, 0);

#pragma unroll 1
    for (int ch = 0; ch < 6; ch++) {
        const int s = ch & 1;
        if (ch < 5) { LD_CHUNK(ch + 1, s ^ 1); CP_WAIT1(); }
        else        { CP_WAIT0(); }
        __syncthreads();

        const __half* Ab = As[s];
        const __half* Bb = Bs[s];
#pragma unroll
        for (int kk = 0; kk < 32; kk += 16) {
            uint32_t af[4][4], bf[6][2];
#pragma unroll
            for (int mi = 0; mi < 4; mi++) {
                const __half* pa = Ab + (wm * 64 + mi * 16 + g) * LDA + kk + 2 * tg;
                af[mi][0] = *(const uint32_t*)(pa);
                af[mi][1] = *(const uint32_t*)(pa + 8 * LDA);
                af[mi][2] = *(const uint32_t*)(pa + 8);
                af[mi][3] = *(const uint32_t*)(pa + 8 * LDA + 8);
            }
#pragma unroll
            for (int ni = 0; ni < 6; ni++) {
                const __half* pb = Bb + (wn * 48 + ni * 8 + g) * LDA + kk + 2 * tg;
                bf[ni][0] = *(const uint32_t*)(pb);
                bf[ni][1] = *(const uint32_t*)(pb + 8);
            }
#pragma unroll
            for (int mi = 0; mi < 4; mi++)
#pragma unroll
                for (int ni = 0; ni < 6; ni++)
                    mma16(c[mi][ni], af[mi], bf[ni]);
        }
        __syncthreads();
    }

    // epilogue: fp16 scatter to window layout
    const int t = nb >> 1;
    __half* qb = g_qkvh + (size_t)t * QT;
#pragma unroll
    for (int mi = 0; mi < 4; mi++) {
#pragma unroll
        for (int half = 0; half < 2; half++) {
            int r = bm + wm * 64 + mi * 16 + g + half * 8;
            int b = r / 3136; int rr = r - b * 3136;
            int y = rr / 56, xx = rr - y * 56;
            int wv = (y / 7) * 8 + (xx / 7);
            int tk = (y % 7) * 7 + (xx % 7);
            __half* base = qb + b * 602112 + wv * 1568 + tk * 32;
#pragma unroll
            for (int ni = 0; ni < 6; ni++) {
                int cp = nb * 96 + wn * 48 + ni * 8 + tg * 2;
                int cc = cp - t * 192;
                int h = cc >> 5, d = cc & 31;
                *(__half2*)(base + h * 100352 + d) =
                    __floats2half2_rn(c[mi][ni][half * 2], c[mi][ni][half * 2 + 1]);
            }
        }
    }
}

// ================= Kernel 2: attention (fp32 compute, fp16 I/O) =================
__global__ __launch_bounds__(256) void attn_kernel(const float* __restrict__ pe)
{
    __shared__ float Qs[52 * 33];
    __shared__ float Ks[52 * 33];
    __shared__ __align__(16) float Vs[49 * 36];
    __shared__ float S [49 * 50];
    __shared__ float PE[169];

    const int tid = threadIdx.x;
    const int bx  = blockIdx.x;
    const int wv  = bx & 63;
    const int wy  = wv >> 3, wx = wv & 7;

    const __half2* qg = (const __half2*)(g_qkvh + (size_t)bx * 1568);
    const __half2* kg = (const __half2*)(g_qkvh + (size_t)QT + (size_t)bx * 1568);
    const __half2* vg = (const __half2*)(g_qkvh + 2 * (size_t)QT + (size_t)bx * 1568);

    if (tid < 99) { Qs[49 * 33 + tid] = 0.f; Ks[49 * 33 + tid] = 0.f; }
    for (int p = tid; p < 784; p += 256) {
        int i = p >> 4, d = (p & 15) * 2;
        float2 q2 = __half22float2(qg[p]);
        float2 k2 = __half22float2(kg[p]);
        float2 v2 = __half22float2(vg[p]);
        Qs[i * 33 + d] = q2.x; Qs[i * 33 + d + 1] = q2.y;
        Ks[i * 33 + d] = k2.x; Ks[i * 33 + d + 1] = k2.y;
        Vs[i * 36 + d] = v2.x; Vs[i * 36 + d + 1] = v2.y;
    }
    for (int p = tid; p < 169; p += 256) PE[p] = pe[p];
    __syncthreads();

    const float scale = 0.17677669529663687f;
    const bool mrow = (wy == 7), mcol = (wx == 7);

    if (tid < 169) {
        const int i0 = (tid / 13) * 4, j0 = (tid % 13) * 4;
        float s[4][4] = {};
#pragma unroll 4
        for (int d = 0; d < 32; d++) {
            float q0 = Qs[(i0 + 0) * 33 + d];
            float q1 = Qs[(i0 + 1) * 33 + d];
            float q2 = Qs[(i0 + 2) * 33 + d];
            float q3 = Qs[(i0 + 3) * 33 + d];
            float k0 = Ks[(j0 + 0) * 33 + d];
            float k1 = Ks[(j0 + 1) * 33 + d];
            float k2 = Ks[(j0 + 2) * 33 + d];
            float k3 = Ks[(j0 + 3) * 33 + d];
            s[0][0] += q0 * k0; s[0][1] += q0 * k1; s[0][2] += q0 * k2; s[0][3] += q0 * k3;
            s[1][0] += q1 * k0; s[1][1] += q1 * k1; s[1][2] += q1 * k2; s[1][3] += q1 * k3;
            s[2][0] += q2 * k0; s[2][1] += q2 * k1; s[2][2] += q2 * k2; s[2][3] += q2 * k3;
            s[3][0] += q3 * k0; s[3][1] += q3 * k1; s[3][2] += q3 * k2; s[3][3] += q3 * k3;
        }
#pragma unroll
        for (int ii = 0; ii < 4; ii++) {
            int i = i0 + ii;
            if (i >= 49) break;
            int iy = i / 7, ix = i - iy * 7;
#pragma unroll
            for (int jj = 0; jj < 4; jj++) {
                int j = j0 + jj;
                if (j >= 49) break;
                int jy = j / 7, jx = j - jy * 7;
                float v = s[ii][jj] * scale + PE[(jy - iy + 6) * 13 + (jx - ix + 6)];
                if (mrow && ((iy >= 4) != (jy >= 4))) v -= 1e9f;
                if (mcol && ((ix >= 4) != (jx >= 4))) v -= 1e9f;
                S[i * 50 + j] = v;
            }
        }
    }
    __syncthreads();

    const int lane = tid & 31, warp = tid >> 5;
    for (int i = warp; i < 49; i += 8) {
        float v0 = S[i * 50 + lane];
        float v1 = (lane < 17) ? S[i * 50 + lane + 32] : -3.4e38f;
        float m = fmaxf(v0, v1);
#pragma unroll
        for (int o = 16; o; o >>= 1) m = fmaxf(m, __shfl_xor_sync(0xffffffffu, m, o));
        float e0 = __expf(v0 - m);
        float e1 = (lane < 17) ? __expf(v1 - m) : 0.f;
        float sm = e0 + e1;
#pragma unroll
        for (int o = 16; o; o >>= 1) sm += __shfl_xor_sync(0xffffffffu, sm, o);
        float inv = 1.f / sm;
        S[i * 50 + lane] = e0 * inv;
        if (lane < 17) S[i * 50 + lane + 32] = e1 * inv;
    }
    __syncthreads();

    __half* og = g_atth + (size_t)bx * 1568;
    if (tid < 200) {
        const int ig = tid >> 3, dg = (tid & 7) * 4;
        const int i0 = ig * 2;
        const bool two = (i0 + 1 < 49);
        float4 a0 = make_float4(0.f, 0.f, 0.f, 0.f);
        float4 a1 = make_float4(0.f, 0.f, 0.f, 0.f);
        const float* s0 = S + i0 * 50;
        const float* s1 = s0 + 50;
#pragma unroll 7
        for (int j = 0; j < 49; j++) {
            float4 v = *(const float4*)(Vs + j * 36 + dg);
            float p0 = s0[j];
            a0.x += p0 * v.x; a0.y += p0 * v.y; a0.z += p0 * v.z; a0.w += p0 * v.w;
            if (two) {
                float p1 = s1[j];
                a1.x += p1 * v.x; a1.y += p1 * v.y; a1.z += p1 * v.z; a1.w += p1 * v.w;
            }
        }
        *(__half2*)(og + (i0 << 5) + dg) = __floats2half2_rn(a0.x, a0.y);
        *(__half2*)(og + (i0 << 5) + dg + 2) = __floats2half2_rn(a0.z, a0.w);
        if (two) {
            *(__half2*)(og + ((i0 + 1) << 5) + dg) = __floats2half2_rn(a1.x, a1.y);
            *(__half2*)(og + ((i0 + 1) << 5) + dg + 2) = __floats2half2_rn(a1.z, a1.w);
        }
    }
}

// ================= Kernel 3: out-proj GEMM + inverse roll =================
__global__ __launch_bounds__(128, 3) void proj_gemm(
    const float* __restrict__ bout, float* __restrict__ out)
{
    __shared__ __align__(16) __half As[2][128 * LDA];
    __shared__ __align__(16) __half Bs[2][96 * LDA];

    const int tid  = threadIdx.x;
    const int warp = tid >> 5, lane = tid & 31;
    const int wm   = warp & 1, wn = warp >> 1;
    const int g    = lane >> 2, tg = lane & 3;
    const int bm   = blockIdx.x * 128;
    const int nb   = blockIdx.y;                 // 0..1

    const __half* abase;
    {
        int row = bm + tid;
        int b = row / 3136; int r = row - b * 3136;
        int y = r / 56, xx = r - y * 56;
        int wv = (y / 7) * 8 + (xx / 7);
        int tk = (y % 7) * 7 + (xx % 7);
        abase = g_atth + b * 602112 + wv * 1568 + tk * 32;  // chunk c = head c
    }
    const int bn = tid >> 2, bq = tid & 3;

    uint32_t a_s[2], b_s[2];
    a_s[0] = smem_u32(As[0]); a_s[1] = smem_u32(As[1]);
    b_s[0] = smem_u32(Bs[0]); b_s[1] = smem_u32(Bs[1]);

#define LD_CHUNK_P(cc, ss) do { \
        uint32_t ad = a_s[ss] + (uint32_t)(tid * LDA) * 2; \
        const __half* asrc = abase + (cc) * 100352; \
        cpa16(ad + 0,  asrc + 0);  cpa16(ad + 16, asrc + 8); \
        cpa16(ad + 32, asrc + 16); cpa16(ad + 48, asrc + 24); \
        _Pragma("unroll") \
        for (int ii = 0; ii < 3; ii++) { \
            int n = bn + ii * 32; \
            cpa16(b_s[ss] + (uint32_t)(n * LDA + bq * 8) * 2, \
                  g_woh + (size_t)(nb * 96 + n) * 192 + (cc) * 32 + bq * 8); \
        } \
        CP_COMMIT(); } while (0)

    float c[4][6][4] = {};
    LD_CHUNK_P(0, 0);

#pragma unroll 1
    for (int ch = 0; ch < 6; ch++) {
        const int s = ch & 1;
        if (ch < 5) { LD_CHUNK_P(ch + 1, s ^ 1); CP_WAIT1(); }
        else        { CP_WAIT0(); }
        __syncthreads();

        const __half* Ab = As[s];
        const __half* Bb = Bs[s];
#pragma unroll
        for (int kk = 0; kk < 32; kk += 16) {
            uint32_t af[4][4], bf[6][2];
#pragma unroll
            for (int mi = 0; mi < 4; mi++) {
                const __half* pa = Ab + (wm * 64 + mi * 16 + g) * LDA + kk + 2 * tg;
                af[mi][0] = *(const uint32_t*)(pa);
                af[mi][1] = *(const uint32_t*)(pa + 8 * LDA);
                af[mi][2] = *(const uint32_t*)(pa + 8);
                af[mi][3] = *(const uint32_t*)(pa + 8 * LDA + 8);
            }
#pragma unroll
            for (int ni = 0; ni < 6; ni++) {
                const __half* pb = Bb + (wn * 48 + ni * 8 + g) * LDA + kk + 2 * tg;
                bf[ni][0] = *(const uint32_t*)(pb);
                bf[ni][1] = *(const uint32_t*)(pb + 8);
            }
#pragma unroll
            for (int mi = 0; mi < 4; mi++)
#pragma unroll
                for (int ni = 0; ni < 6; ni++)
                    mma16(c[mi][ni], af[mi], bf[ni]);
        }
        __syncthreads();
    }

    // epilogue: bias + inverse roll, fp32 out
#pragma unroll
    for (int mi = 0; mi < 4; mi++) {
#pragma unroll
        for (int half = 0; half < 2; half++) {
            int r = bm + wm * 64 + mi * 16 + g + half * 8;
            int b = r / 3136; int rr = r - b * 3136;
            int y = rr / 56, xx = rr - y * 56;
            int yo = y + 3;  if (yo >= 56) yo -= 56;
            int xo = xx + 3; if (xo >= 56) xo -= 56;
            float* op = out + ((b * 56 + yo) * 56 + xo) * 192;
#pragma unroll
            for (int ni = 0; ni < 6; ni++) {
                int cp = nb * 96 + wn * 48 + ni * 8 + tg * 2;
                float2 bb = *(const float2*)(bout + cp);
                float2 v = make_float2(c[mi][ni][half * 2] + bb.x,
                                       c[mi][ni][half * 2 + 1] + bb.y);
                *(float2*)(op + cp) = v;
            }
        }
    }
}

// ================= launch =================
extern "C" void kernel_launch(void* const* d_in, const int* in_sizes, int n_in,
                              void* d_out, int out_size)
{
    const float* x    = (const float*)d_in[0];
    const float* wqkv = (const float*)d_in[1];
    const float* pe   = (const float*)d_in[2];
    const float* wout = (const float*)d_in[3];
    const float* bout = (const float*)d_in[4];
    float* out = (float*)d_out;

    prep_x<<<9408, 256>>>(x);
    prep_w<<<108, 256>>>(wqkv);
    prep_wo<<<36, 256>>>(wout);

    dim3 g1(392, 6);
    qkv_gemm<<<g1, 128>>>();

    attn_kernel<<<16 * 6 * 64, 256>>>(pe);

    dim3 g3(392, 2);
    proj_gemm<<<g3, 128>>>(bout, out);
}

// round 6
// speedup vs baseline: 3.7223x; 1.4032x over previous
#include <cuda_runtime.h>
#include <cuda_fp16.h>
#include <cstdint>

#define QT (16*6*64*49*32)            // 9,633,792 elements per q/k/v tensor

__device__ __half g_xh[50176 * 192];  // rolled x, fp16, token-major
__device__ __half g_wh[576 * 192];    // wqkv^T [n][k] fp16
__device__ __half g_woh[192 * 192];   // wout^T [n][k] fp16
__device__ __half g_qkvh[3u * QT];    // q|k|v fp16, window layout [b,h,win,49,32]
__device__ __half g_atth[QT];         // attention out fp16, window layout

// ---------------- helpers ----------------
__device__ __forceinline__ void mma16(float* c, const uint32_t* a, const uint32_t* b) {
    asm volatile("mma.sync.aligned.m16n8k16.row.col.f32.f16.f16.f32 "
        "{%0,%1,%2,%3}, {%4,%5,%6,%7}, {%8,%9}, {%0,%1,%2,%3};\n"
        : "+f"(c[0]), "+f"(c[1]), "+f"(c[2]), "+f"(c[3])
        : "r"(a[0]), "r"(a[1]), "r"(a[2]), "r"(a[3]), "r"(b[0]), "r"(b[1]));
}
__device__ __forceinline__ void cpa16(uint32_t s, const void* g) {
    asm volatile("cp.async.cg.shared.global [%0], [%1], 16;" :: "r"(s), "l"(g));
}
#define CP_COMMIT() asm volatile("cp.async.commit_group;")
#define CP_WAIT1()  asm volatile("cp.async.wait_group 1;")
#define CP_WAIT0()  asm volatile("cp.async.wait_group 0;")
__device__ __forceinline__ uint32_t smem_u32(const void* p) {
    uint32_t a;
    asm("{ .reg .u64 t; cvta.to.shared.u64 t, %1; cvt.u32.u64 %0, t; }" : "=r"(a) : "l"(p));
    return a;
}
__device__ __forceinline__ uint32_t h2u(__half2 h) { return *reinterpret_cast<uint32_t*>(&h); }

// ================= prep kernels =================
__global__ __launch_bounds__(256) void prep_x(const float* __restrict__ x) {
    int i = blockIdx.x * 256 + threadIdx.x;
    int e = i * 4;
    int t = e / 192, c = e - t * 192;
    int b = t / 3136; int r = t - b * 3136;
    int y = r / 56, xx = r - y * 56;
    int ys = y + 3;  if (ys >= 56) ys -= 56;
    int xs = xx + 3; if (xs >= 56) xs -= 56;
    float4 v = *(const float4*)(x + ((b * 56 + ys) * 56 + xs) * 192 + c);
    *(__half2*)(g_xh + e)     = __floats2half2_rn(v.x, v.y);
    *(__half2*)(g_xh + e + 2) = __floats2half2_rn(v.z, v.w);
}
__global__ __launch_bounds__(256) void prep_w(const float* __restrict__ w) {
    int i = blockIdx.x * 256 + threadIdx.x;
    int e = i * 4;
    int n = e / 192, k = e - n * 192;
#pragma unroll
    for (int j = 0; j < 4; j++)
        g_wh[e + j] = __float2half_rn(w[(k + j) * 576 + n]);
}
__global__ __launch_bounds__(256) void prep_wo(const float* __restrict__ w) {
    int i = blockIdx.x * 256 + threadIdx.x;
    int e = i * 4;
    int n = e / 192, k = e - n * 192;
#pragma unroll
    for (int j = 0; j < 4; j++)
        g_woh[e + j] = __float2half_rn(w[(k + j) * 192 + n]);
}

// ============ fp16 GEMM: BM=128, BN=96, BK=32, 128 threads (4 warps 2x2) ============
#define LDA 40

// ================= Kernel 1: QKV GEMM =================
__global__ __launch_bounds__(128, 3) void qkv_gemm(void)
{
    __shared__ __align__(16) __half As[2][128 * LDA];
    __shared__ __align__(16) __half Bs[2][96 * LDA];

    const int tid  = threadIdx.x;
    const int warp = tid >> 5, lane = tid & 31;
    const int wm   = warp & 1, wn = warp >> 1;
    const int g    = lane >> 2, tg = lane & 3;
    const int bm   = blockIdx.x * 128;
    const int nb   = blockIdx.y;

    const __half* ap = g_xh + (size_t)(bm + tid) * 192;
    const int bn = tid >> 2, bq = tid & 3;

    uint32_t a_s[2], b_s[2];
    a_s[0] = smem_u32(As[0]); a_s[1] = smem_u32(As[1]);
    b_s[0] = smem_u32(Bs[0]); b_s[1] = smem_u32(Bs[1]);

#define LD_CHUNK(cc, ss) do { \
        uint32_t ad = a_s[ss] + (uint32_t)(tid * LDA) * 2; \
        const __half* asrc = ap + (cc) * 32; \
        cpa16(ad + 0,  asrc + 0);  cpa16(ad + 16, asrc + 8); \
        cpa16(ad + 32, asrc + 16); cpa16(ad + 48, asrc + 24); \
        _Pragma("unroll") \
        for (int ii = 0; ii < 3; ii++) { \
            int n = bn + ii * 32; \
            cpa16(b_s[ss] + (uint32_t)(n * LDA + bq * 8) * 2, \
                  g_wh + (size_t)(nb * 96 + n) * 192 + (cc) * 32 + bq * 8); \
        } \
        CP_COMMIT(); } while (0)

    float c[4][6][4] = {};
    LD_CHUNK(0, 0);

#pragma unroll 1
    for (int ch = 0; ch < 6; ch++) {
        const int s = ch & 1;
        if (ch < 5) { LD_CHUNK(ch + 1, s ^ 1); CP_WAIT1(); }
        else        { CP_WAIT0(); }
        __syncthreads();

        const __half* Ab = As[s];
        const __half* Bb = Bs[s];
#pragma unroll
        for (int kk = 0; kk < 32; kk += 16) {
            uint32_t af[4][4], bf[6][2];
#pragma unroll
            for (int mi = 0; mi < 4; mi++) {
                const __half* pa = Ab + (wm * 64 + mi * 16 + g) * LDA + kk + 2 * tg;
                af[mi][0] = *(const uint32_t*)(pa);
                af[mi][1] = *(const uint32_t*)(pa + 8 * LDA);
                af[mi][2] = *(const uint32_t*)(pa + 8);
                af[mi][3] = *(const uint32_t*)(pa + 8 * LDA + 8);
            }
#pragma unroll
            for (int ni = 0; ni < 6; ni++) {
                const __half* pb = Bb + (wn * 48 + ni * 8 + g) * LDA + kk + 2 * tg;
                bf[ni][0] = *(const uint32_t*)(pb);
                bf[ni][1] = *(const uint32_t*)(pb + 8);
            }
#pragma unroll
            for (int mi = 0; mi < 4; mi++)
#pragma unroll
                for (int ni = 0; ni < 6; ni++)
                    mma16(c[mi][ni], af[mi], bf[ni]);
        }
        __syncthreads();
    }

    const int t = nb >> 1;
    __half* qb = g_qkvh + (size_t)t * QT;
#pragma unroll
    for (int mi = 0; mi < 4; mi++) {
#pragma unroll
        for (int half = 0; half < 2; half++) {
            int r = bm + wm * 64 + mi * 16 + g + half * 8;
            int b = r / 3136; int rr = r - b * 3136;
            int y = rr / 56, xx = rr - y * 56;
            int wv = (y / 7) * 8 + (xx / 7);
            int tk = (y % 7) * 7 + (xx % 7);
            __half* base = qb + b * 602112 + wv * 1568 + tk * 32;
#pragma unroll
            for (int ni = 0; ni < 6; ni++) {
                int cp = nb * 96 + wn * 48 + ni * 8 + tg * 2;
                int cc = cp - t * 192;
                int h = cc >> 5, d = cc & 31;
                *(__half2*)(base + h * 100352 + d) =
                    __floats2half2_rn(c[mi][ni][half * 2], c[mi][ni][half * 2 + 1]);
            }
        }
    }
}

// ================= Kernel 2: HMMA attention =================
// Block = one window-head. 128 threads = 4 warps; warp w owns query rows [w*16, w*16+16).
// S (64x64 padded) via m16n8k16; softmax in registers (quad shuffles); P repacked
// from accumulators as A-fragments; O = P @ V via Vt smem.
#define LDQ 40   // halves per row of Qs/Ks (words: r*20+t distinct mod 32)
#define LDV 72   // halves per row of Vt  (words: d*36+t distinct mod 32)

__global__ __launch_bounds__(128) void attn_hmma(const float* __restrict__ pe)
{
    __shared__ __align__(16) __half Qs[64 * LDQ];
    __shared__ __align__(16) __half Ks[64 * LDQ];
    __shared__ __align__(16) __half Vt[32 * LDV];
    __shared__ float PE[169];

    const int tid = threadIdx.x;
    const int w = tid >> 5, lane = tid & 31;
    const int g = lane >> 2, t = lane & 3;
    const int bx = blockIdx.x;
    const int wv = bx & 63;
    const int wy = wv >> 3, wx = wv & 7;
    const bool mrow = (wy == 7), mcol = (wx == 7);

    const __half2* qg = (const __half2*)(g_qkvh + (size_t)bx * 1568);
    const __half2* kg = (const __half2*)(g_qkvh + (size_t)QT + (size_t)bx * 1568);
    const __half2* vg = (const __half2*)(g_qkvh + 2 * (size_t)QT + (size_t)bx * 1568);

    // load Q,K (zero-pad rows 49..63), V transposed (zero-pad cols 49..63)
    const __half2 z2 = __floats2half2_rn(0.f, 0.f);
    for (int p = tid; p < 1280; p += 128) {      // 64 rows x 20 half2
        int i = p / 20, dp = p - i * 20;
        __half2 qv = z2, kv = z2;
        if (dp < 16 && i < 49) { qv = qg[i * 16 + dp]; kv = kg[i * 16 + dp]; }
        *(__half2*)(Qs + i * LDQ + dp * 2) = qv;
        *(__half2*)(Ks + i * LDQ + dp * 2) = kv;
    }
    for (int p = tid; p < 784; p += 128) {       // V[i][2dp,2dp+1] -> Vt
        int i = p >> 4, dp = p & 15;
        __half2 v = vg[p];
        Vt[(2 * dp) * LDV + i]     = __low2half(v);
        Vt[(2 * dp + 1) * LDV + i] = __high2half(v);
    }
    for (int p = tid; p < 480; p += 128) {       // zero Vt cols 49..63
        int d = p / 15, c = 49 + (p - d * 15);
        Vt[d * LDV + c] = __float2half_rn(0.f);
    }
    for (int p = tid; p < 169; p += 128) PE[p] = pe[p];
    __syncthreads();

    // ---- S = Q K^T (warp rows w*16..w*16+15, all 64 padded cols) ----
    float S[8][4] = {};
    const __half* qrow = Qs + (w * 16 + g) * LDQ;
#pragma unroll
    for (int kk = 0; kk < 32; kk += 16) {
        uint32_t a[4];
        a[0] = *(const uint32_t*)(qrow + kk + 2 * t);
        a[1] = *(const uint32_t*)(qrow + 8 * LDQ + kk + 2 * t);
        a[2] = *(const uint32_t*)(qrow + kk + 8 + 2 * t);
        a[3] = *(const uint32_t*)(qrow + 8 * LDQ + kk + 8 + 2 * t);
#pragma unroll
        for (int n = 0; n < 8; n++) {
            uint32_t b[2];
            const __half* kb = Ks + (n * 8 + g) * LDQ + kk + 2 * t;
            b[0] = *(const uint32_t*)(kb);
            b[1] = *(const uint32_t*)(kb + 8);
            mma16(S[n], a, b);
        }
    }

    // ---- bias + mask + softmax (registers; rows g and g+8 per lane) ----
    const float scale = 0.17677669529663687f;
#pragma unroll
    for (int rw = 0; rw < 2; rw++) {
        int i = w * 16 + g + rw * 8;
        int ic = (i < 49) ? i : 48;              // clamp (padded rows are discarded)
        int iy = ic / 7, ix = ic - iy * 7;
        float mx = -1e30f;
#pragma unroll
        for (int n = 0; n < 8; n++) {
#pragma unroll
            for (int e = 0; e < 2; e++) {
                int j = n * 8 + 2 * t + e;
                float v;
                if (j < 49) {
                    int jy = j / 7, jx = j - jy * 7;
                    v = S[n][rw * 2 + e] * scale + PE[(jy - iy + 6) * 13 + (jx - ix + 6)];
                    if (mrow && ((iy >= 4) != (jy >= 4))) v -= 1e9f;
                    if (mcol && ((ix >= 4) != (jx >= 4))) v -= 1e9f;
                } else {
                    v = -1e9f;
                }
                S[n][rw * 2 + e] = v;
                mx = fmaxf(mx, v);
            }
        }
        mx = fmaxf(mx, __shfl_xor_sync(0xffffffffu, mx, 1));
        mx = fmaxf(mx, __shfl_xor_sync(0xffffffffu, mx, 2));
        float sm = 0.f;
#pragma unroll
        for (int n = 0; n < 8; n++) {
#pragma unroll
            for (int e = 0; e < 2; e++) {
                float ex = __expf(S[n][rw * 2 + e] - mx);
                S[n][rw * 2 + e] = ex;
                sm += ex;
            }
        }
        sm += __shfl_xor_sync(0xffffffffu, sm, 1);
        sm += __shfl_xor_sync(0xffffffffu, sm, 2);
        float inv = 1.f / sm;
#pragma unroll
        for (int n = 0; n < 8; n++) {
            S[n][rw * 2 + 0] *= inv;
            S[n][rw * 2 + 1] *= inv;
        }
    }

    // ---- repack P accumulators into A-fragments (no shuffles) ----
    uint32_t Pa[4][4];
#pragma unroll
    for (int c = 0; c < 4; c++) {
        Pa[c][0] = h2u(__floats2half2_rn(S[2 * c][0],     S[2 * c][1]));
        Pa[c][1] = h2u(__floats2half2_rn(S[2 * c][2],     S[2 * c][3]));
        Pa[c][2] = h2u(__floats2half2_rn(S[2 * c + 1][0], S[2 * c + 1][1]));
        Pa[c][3] = h2u(__floats2half2_rn(S[2 * c + 1][2], S[2 * c + 1][3]));
    }

    // ---- O = P V ----
    float O[4][4] = {};
#pragma unroll
    for (int c = 0; c < 4; c++) {
#pragma unroll
        for (int nt = 0; nt < 4; nt++) {
            uint32_t b[2];
            const __half* vb = Vt + (nt * 8 + g) * LDV + c * 16 + 2 * t;
            b[0] = *(const uint32_t*)(vb);
            b[1] = *(const uint32_t*)(vb + 8);
            mma16(O[nt], Pa[c], b);
        }
    }

    // ---- store fp16 ----
    __half* og = g_atth + (size_t)bx * 1568;
#pragma unroll
    for (int rw = 0; rw < 2; rw++) {
        int i = w * 16 + g + rw * 8;
        if (i < 49) {
#pragma unroll
            for (int nt = 0; nt < 4; nt++)
                *(__half2*)(og + i * 32 + nt * 8 + 2 * t) =
                    __floats2half2_rn(O[nt][rw * 2], O[nt][rw * 2 + 1]);
        }
    }
}

// ================= Kernel 3: out-proj GEMM + inverse roll =================
__global__ __launch_bounds__(128, 3) void proj_gemm(
    const float* __restrict__ bout, float* __restrict__ out)
{
    __shared__ __align__(16) __half As[2][128 * LDA];
    __shared__ __align__(16) __half Bs[2][96 * LDA];

    const int tid  = threadIdx.x;
    const int warp = tid >> 5, lane = tid & 31;
    const int wm   = warp & 1, wn = warp >> 1;
    const int g    = lane >> 2, tg = lane & 3;
    const int bm   = blockIdx.x * 128;
    const int nb   = blockIdx.y;

    const __half* abase;
    {
        int row = bm + tid;
        int b = row / 3136; int r = row - b * 3136;
        int y = r / 56, xx = r - y * 56;
        int wv = (y / 7) * 8 + (xx / 7);
        int tk = (y % 7) * 7 + (xx % 7);
        abase = g_atth + b * 602112 + wv * 1568 + tk * 32;
    }
    const int bn = tid >> 2, bq = tid & 3;

    uint32_t a_s[2], b_s[2];
    a_s[0] = smem_u32(As[0]); a_s[1] = smem_u32(As[1]);
    b_s[0] = smem_u32(Bs[0]); b_s[1] = smem_u32(Bs[1]);

#define LD_CHUNK_P(cc, ss) do { \
        uint32_t ad = a_s[ss] + (uint32_t)(tid * LDA) * 2; \
        const __half* asrc = abase + (cc) * 100352; \
        cpa16(ad + 0,  asrc + 0);  cpa16(ad + 16, asrc + 8); \
        cpa16(ad + 32, asrc + 16); cpa16(ad + 48, asrc + 24); \
        _Pragma("unroll") \
        for (int ii = 0; ii < 3; ii++) { \
            int n = bn + ii * 32; \
            cpa16(b_s[ss] + (uint32_t)(n * LDA + bq * 8) * 2, \
                  g_woh + (size_t)(nb * 96 + n) * 192 + (cc) * 32 + bq * 8); \
        } \
        CP_COMMIT(); } while (0)

    float c[4][6][4] = {};
    LD_CHUNK_P(0, 0);

#pragma unroll 1
    for (int ch = 0; ch < 6; ch++) {
        const int s = ch & 1;
        if (ch < 5) { LD_CHUNK_P(ch + 1, s ^ 1); CP_WAIT1(); }
        else        { CP_WAIT0(); }
        __syncthreads();

        const __half* Ab = As[s];
        const __half* Bb = Bs[s];
#pragma unroll
        for (int kk = 0; kk < 32; kk += 16) {
            uint32_t af[4][4], bf[6][2];
#pragma unroll
            for (int mi = 0; mi < 4; mi++) {
                const __half* pa = Ab + (wm * 64 + mi * 16 + g) * LDA + kk + 2 * tg;
                af[mi][0] = *(const uint32_t*)(pa);
                af[mi][1] = *(const uint32_t*)(pa + 8 * LDA);
                af[mi][2] = *(const uint32_t*)(pa + 8);
                af[mi][3] = *(const uint32_t*)(pa + 8 * LDA + 8);
            }
#pragma unroll
            for (int ni = 0; ni < 6; ni++) {
                const __half* pb = Bb + (wn * 48 + ni * 8 + g) * LDA + kk + 2 * tg;
                bf[ni][0] = *(const uint32_t*)(pb);
                bf[ni][1] = *(const uint32_t*)(pb + 8);
            }
#pragma unroll
            for (int mi = 0; mi < 4; mi++)
#pragma unroll
                for (int ni = 0; ni < 6; ni++)
                    mma16(c[mi][ni], af[mi], bf[ni]);
        }
        __syncthreads();
    }

#pragma unroll
    for (int mi = 0; mi < 4; mi++) {
#pragma unroll
        for (int half = 0; half < 2; half++) {
            int r = bm + wm * 64 + mi * 16 + g + half * 8;
            int b = r / 3136; int rr = r - b * 3136;
            int y = rr / 56, xx = rr - y * 56;
            int yo = y + 3;  if (yo >= 56) yo -= 56;
            int xo = xx + 3; if (xo >= 56) xo -= 56;
            float* op = out + ((b * 56 + yo) * 56 + xo) * 192;
#pragma unroll
            for (int ni = 0; ni < 6; ni++) {
                int cp = nb * 96 + wn * 48 + ni * 8 + tg * 2;
                float2 bb = *(const float2*)(bout + cp);
                float2 v = make_float2(c[mi][ni][half * 2] + bb.x,
                                       c[mi][ni][half * 2 + 1] + bb.y);
                *(float2*)(op + cp) = v;
            }
        }
    }
}

// ================= launch =================
extern "C" void kernel_launch(void* const* d_in, const int* in_sizes, int n_in,
                              void* d_out, int out_size)
{
    const float* x    = (const float*)d_in[0];
    const float* wqkv = (const float*)d_in[1];
    const float* pe   = (const float*)d_in[2];
    const float* wout = (const float*)d_in[3];
    const float* bout = (const float*)d_in[4];
    float* out = (float*)d_out;

    prep_x<<<9408, 256>>>(x);
    prep_w<<<108, 256>>>(wqkv);
    prep_wo<<<36, 256>>>(wout);

    dim3 g1(392, 6);
    qkv_gemm<<<g1, 128>>>();

    attn_hmma<<<16 * 6 * 64, 128>>>(pe);

    dim3 g3(392, 2);
    proj_gemm<<<g3, 128>>>(bout, out);
}